// round 10
// baseline (speedup 1.0000x reference)
#include <cuda_runtime.h>
#include <cstdint>

#define NBATCH 4
#define NA 25200
#define NCLS 80
#define ROWF 85
#define ATTNF 980
#define AR 14
#define CONF 0.25f
#define IOUT 0.45f
#define MAXDET 100
#define TOPK 1024
#define HB 256
#define MAXC 2048
#define PRECAP 16384
#define PREV 0.9f
#define HW 160
#define OUTROW 25606
#define SCB (NA * NCLS)          // 2,016,000 scores per batch

// ---------------- scratch (device globals; zero-init at load) ---------------
__device__ int                g_preCnt[NBATCH];
__device__ unsigned long long g_preKey[NBATCH * PRECAP];
__device__ int                g_detAnchor[NBATCH * MAXDET];

// ---------------- pass 1: streaming prefilter (v > 0.9) ---------------------
__global__ void __launch_bounds__(256) k_pre(const float* __restrict__ test) {
    int i = blockIdx.x * 256 + threadIdx.x;          // 0 .. 4*SCB-1
    int b = i / SCB;
    int rem = i - b * SCB;
    int a = rem / NCLS;
    int c = rem - a * NCLS;
    const float* row = test + ((size_t)b * NA + a) * ROWF;
    float v = __ldg(row + 5 + c) * __ldg(row + 4);
    if (v > PREV) {
        int pos = atomicAdd(&g_preCnt[b], 1);
        if (pos < PRECAP) {
            unsigned flat = (unsigned)rem;
            g_preKey[b * PRECAP + pos] =
                ((unsigned long long)__float_as_uint(v) << 32) |
                (unsigned long long)(0xFFFFFFFFu - flat);
        }
    }
}

// ---------------- hybrid bitonic helpers ------------------------------------
__device__ __forceinline__ unsigned long long cex_shfl(unsigned long long v, int i, int j, int k) {
    unsigned long long pv = __shfl_xor_sync(0xFFFFFFFFu, v, j);
    bool lower = ((i & j) == 0);
    bool desc  = ((i & k) == 0);
    return (desc == lower) ? (v > pv ? v : pv) : (v < pv ? v : pv);
}
__device__ __forceinline__ void cex_reg(unsigned long long& v0, unsigned long long& v1, int i0, int k) {
    bool desc = ((i0 & k) == 0);
    unsigned long long a = v0, b = v1;
    if (desc ? (a < b) : (a > b)) { v0 = b; v1 = a; }
}

// ---------------- hist + filter + bitonic sort + greedy NMS -----------------
union SortU {
    unsigned long long s[MAXC];
    struct { int cls[TOPK]; int anc[TOPK]; } post;
};

__global__ void __launch_bounds__(1024, 1) k_sortnms(const float* __restrict__ test,
                                                     float* __restrict__ out) {
    __shared__ SortU u;
    __shared__ float sbx1[TOPK], sby1[TOPK], sbx2[TOPK], sby2[TOPK], sar[TOPK], sval[TOPK];
    __shared__ unsigned int hh[HB];
    __shared__ unsigned int vword[TOPK / 32];
    __shared__ int sel[MAXDET];
    __shared__ int s_thr, s_cnt;
    const int b = blockIdx.x;
    const int t = threadIdx.x;
    const int lane = t & 31, wid = t >> 5;
    const int base = wid * 64;
    const int i0 = base + lane, i1 = base + 32 + lane;

    if (t < HB) hh[t] = 0u;
    if (t == 0) s_cnt = 0;
    __syncthreads();

    const int rawCnt = g_preCnt[b];
    const int n = rawCnt > PRECAP ? PRECAP : rawCnt;
    const bool usePre = (rawCnt <= PRECAP) && (rawCnt >= TOPK);

    // phase 1: histogram
    if (usePre) {
        for (int i = t; i < n; i += 1024) {
            float v = __uint_as_float((unsigned)(g_preKey[b * PRECAP + i] >> 32));
            int bin = (int)(v * 256.0f); bin = bin > 255 ? 255 : bin;
            atomicAdd(&hh[bin], 1u);
        }
    } else {
        const float* tb = test + (size_t)b * NA * ROWF;
        for (int i = t; i < SCB; i += 1024) {
            int a = i / NCLS, c = i - a * NCLS;
            float v = tb[a * ROWF + 5 + c] * tb[a * ROWF + 4];
            if (v > CONF) {
                int bin = (int)(v * 256.0f); bin = bin > 255 ? 255 : bin;
                atomicAdd(&hh[bin], 1u);
            }
        }
    }
    __syncthreads();

    // phase 2: threshold bin (warp 0): highest bin whose suffix >= TOPK
    if (t < 32) {
        unsigned h[8];
#pragma unroll
        for (int k = 0; k < 8; k++) h[k] = hh[lane * 8 + k];
        unsigned tot = 0;
#pragma unroll
        for (int k = 0; k < 8; k++) tot += h[k];
        unsigned run = tot;
#pragma unroll
        for (int off = 1; off < 32; off <<= 1) {
            unsigned v = __shfl_down_sync(0xFFFFFFFFu, run, off);
            if (lane + off < 32) run += v;
        }
        unsigned above = run - tot;
        int cand = -1;
        unsigned cum = above;
        for (int k = 7; k >= 0; k--) {
            cum += h[k];
            if (cum >= TOPK) { cand = lane * 8 + k; break; }
        }
#pragma unroll
        for (int off = 16; off > 0; off >>= 1)
            cand = max(cand, __shfl_xor_sync(0xFFFFFFFFu, cand, off));
        if (lane == 0) s_thr = cand < 0 ? 0 : cand;
    }
    __syncthreads();
    const int thr = s_thr;

    // phase 3: gather candidates with bin >= thr
    if (usePre) {
        for (int i = t; i < n; i += 1024) {
            unsigned long long key = g_preKey[b * PRECAP + i];
            float v = __uint_as_float((unsigned)(key >> 32));
            int bin = (int)(v * 256.0f); bin = bin > 255 ? 255 : bin;
            if (bin >= thr) {
                int pos = atomicAdd(&s_cnt, 1);
                if (pos < MAXC) u.s[pos] = key;
            }
        }
    } else {
        const float* tb = test + (size_t)b * NA * ROWF;
        for (int i = t; i < SCB; i += 1024) {
            int a = i / NCLS, c = i - a * NCLS;
            float v = tb[a * ROWF + 5 + c] * tb[a * ROWF + 4];
            if (v > CONF) {
                int bin = (int)(v * 256.0f); bin = bin > 255 ? 255 : bin;
                if (bin >= thr) {
                    int pos = atomicAdd(&s_cnt, 1);
                    if (pos < MAXC)
                        u.s[pos] = ((unsigned long long)__float_as_uint(v) << 32) |
                                   (unsigned long long)(0xFFFFFFFFu - (unsigned)i);
                }
            }
        }
    }
    __syncthreads();
    int cnt = s_cnt; if (cnt > MAXC) cnt = MAXC;
    for (int i = t; i < MAXC; i += 1024)
        if (i >= cnt) u.s[i] = 0x00000000FFFFFFFFull;
    __syncthreads();

    // bitonic sort 2048 (hybrid: warp-local j<=32, smem j>=64)
    unsigned long long v0 = u.s[i0];
    unsigned long long v1 = u.s[i1];
#pragma unroll
    for (int k = 2; k <= 64; k <<= 1) {
#pragma unroll
        for (int j = k >> 1; j >= 1; j >>= 1) {
            if (j == 32) cex_reg(v0, v1, i0, k);
            else { v0 = cex_shfl(v0, i0, j, k); v1 = cex_shfl(v1, i1, j, k); }
        }
    }
    u.s[i0] = v0; u.s[i1] = v1;
    __syncthreads();
    for (int k = 128; k <= MAXC; k <<= 1) {
        for (int j = k >> 1; j >= 64; j >>= 1) {
#pragma unroll
            for (int i = t; i < MAXC; i += 1024) {
                int ixj = i ^ j;
                if (ixj > i) {
                    unsigned long long a = u.s[i], bb = u.s[ixj];
                    bool up = (i & k) == 0;
                    if (up ? (a < bb) : (a > bb)) { u.s[i] = bb; u.s[ixj] = a; }
                }
            }
            __syncthreads();
        }
        v0 = u.s[i0]; v1 = u.s[i1];
        cex_reg(v0, v1, i0, k);
#pragma unroll
        for (int j = 16; j >= 1; j >>= 1) {
            v0 = cex_shfl(v0, i0, j, k);
            v1 = cex_shfl(v1, i1, j, k);
        }
        u.s[i0] = v0; u.s[i1] = v1;
        __syncthreads();
    }

    unsigned long long key = u.s[t];
    __syncthreads();

    float v = __uint_as_float((unsigned)(key >> 32));
    unsigned flat = 0xFFFFFFFFu - (unsigned)(key & 0xFFFFFFFFull);
    bool valid = v > CONF;
    int anc = valid ? (int)(flat / NCLS) : 0;
    int cls = valid ? (int)(flat - (unsigned)anc * NCLS) : 0;

    const float* r = test + ((size_t)b * NA + anc) * ROWF;
    float cx = r[0], cy = r[1], w = r[2], h = r[3];
    float x1 = cx - 0.5f * w, y1 = cy - 0.5f * h;
    float x2 = cx + 0.5f * w, y2 = cy + 0.5f * h;
    sbx1[t] = x1; sby1[t] = y1; sbx2[t] = x2; sby2[t] = y2;
    sar[t] = fmaxf(x2 - x1, 0.f) * fmaxf(y2 - y1, 0.f);
    sval[t] = v; u.post.cls[t] = cls; u.post.anc[t] = anc;

    unsigned bal = __ballot_sync(0xFFFFFFFFu, valid);
    if (lane == 0) vword[wid] = bal;

    // zero scratch for next replay
    if (t == 0) g_preCnt[b] = 0;
    __syncthreads();

    for (int det = 0; det < MAXDET; det++) {
        unsigned m   = vword[lane];
        unsigned act = __ballot_sync(0xFFFFFFFFu, m != 0);
        int wsel = act ? (__ffs(act) - 1) : 0;
        unsigned mw = __shfl_sync(0xFFFFFFFFu, m, wsel);
        int j = act ? (wsel * 32 + __ffs(mw) - 1) : -1;
        if (t == 0) sel[det] = j;

        bool sup = false;
        if (j >= 0 && ((vword[wid] >> lane) & 1u)) {
            if (t == j) sup = true;
            else if (cls == u.post.cls[j]) {
                float lx = fmaxf(x1, sbx1[j]), ly = fmaxf(y1, sby1[j]);
                float rx = fminf(x2, sbx2[j]), ry = fminf(y2, sby2[j]);
                float iw = fmaxf(rx - lx, 0.f), ih = fmaxf(ry - ly, 0.f);
                float inter = iw * ih;
                float iou = inter / (sar[t] + sar[j] - inter + 1e-9f);
                sup = iou > IOUT;
            }
        }
        unsigned sm = __ballot_sync(0xFFFFFFFFu, sup);
        if (lane == 0) vword[wid] &= ~sm;
        __syncthreads();
    }

    // parallel epilogue: det headers
    if (t < MAXDET) {
        int j = sel[t];
        size_t ob = (size_t)(b * MAXDET + t) * OUTROW;
        if (j >= 0) {
            out[ob + 0] = sbx1[j]; out[ob + 1] = sby1[j];
            out[ob + 2] = sbx2[j]; out[ob + 3] = sby2[j];
            out[ob + 4] = sval[j]; out[ob + 5] = (float)u.post.cls[j];
            g_detAnchor[b * MAXDET + t] = u.post.anc[j];
        } else {
            out[ob+0]=0.f; out[ob+1]=0.f; out[ob+2]=0.f;
            out[ob+3]=0.f; out[ob+4]=0.f; out[ob+5]=0.f;
            g_detAnchor[b * MAXDET + t] = 0;
        }
    }
}

// ---------------- masks: 1 det/block, reg x-params, reduced MUFU ------------
// dynamic smem (floats): sA 0..980 | patch 980..6260 | per-warp 16*470
#define MSK_SMEM_FLOATS (6260 + 16 * 470)
#define MSK_SMEM_BYTES  (MSK_SMEM_FLOATS * 4)

__device__ __forceinline__ float tanh_approx(float x) {
    float r;
    asm("tanh.approx.f32 %0, %1;" : "=f"(r) : "f"(x));
    return r;
}

__global__ void __launch_bounds__(512, 3) k_masks(const float* __restrict__ test,
                        const float* __restrict__ attn,
                        const float* __restrict__ bases,
                        const float* __restrict__ sem,
                        float* __restrict__ out) {
    extern __shared__ float dyn[];
    float* sA    = dyn;
    float* patch = dyn + 980;
    const int b   = blockIdx.y;
    const int det = blockIdx.x;
    const int t   = threadIdx.x;
    const int lane = t & 31, wid = t >> 5;
    const int anc = g_detAnchor[b * MAXDET + det];

    float2* rows2 = (float2*)(dyn + 6260 + wid * 470);        // 160 float2
    float2* tw2   = (float2*)(dyn + 6260 + wid * 470 + 320);  // 75 float2

    const float* r = test + ((size_t)b * NA + anc) * ROWF;
    float cx = __ldg(r), cy = __ldg(r + 1), w = __ldg(r + 2), h = __ldg(r + 3);
    float bx1 = cx - 0.5f * w, by1 = cy - 0.5f * h;
    float bx2 = cx + 0.5f * w, by2 = cy + 0.5f * h;
    float X1 = bx1 * 0.25f - 0.5f, Y1 = by1 * 0.25f - 0.5f;
    float X2 = bx2 * 0.25f - 0.5f, Y2 = by2 * 0.25f - 0.5f;
    float DX = (X2 - X1) / (float)HW;
    float DY = (Y2 - Y1) / (float)HW;

    float sxa = X1 + 0.5f * DX;
    int x_lo  = (int)floorf(fminf(fmaxf(sxa, 0.f), 159.f));
    float sya = Y1 + 0.5f * DY;
    int y_lo  = (int)floorf(fminf(fmaxf(sya, 0.f), 159.f));

    {
        const float4* ap = (const float4*)(attn + ((size_t)b * NA + anc) * ATTNF);
        for (int i = t; i < ATTNF / 4; i += 512) ((float4*)sA)[i] = ap[i];
    }
#pragma unroll
    for (int c = 0; c < 5; c++) {
        const float* F = (c < 4) ? bases + (size_t)(b * 4 + c) * (HW * HW)
                                 : sem + (size_t)b * (HW * HW);
        for (int i = t; i < 32 * 32; i += 512) {
            int yy = i >> 5, xx = i & 31;
            int gy = min(y_lo + yy, HW - 1);
            int gx = min(x_lo + xx, HW - 1);
            patch[(c * 32 + yy) * 33 + xx] = __ldg(F + gy * HW + gx);
        }
    }
    __syncthreads();

    // per-thread x params (fixed across rows)
    float fxs[5], wcxs[5];
    int   xps[5], cxs[5];
    unsigned vmask = 0;
#pragma unroll
    for (int sub = 0; sub < 5; sub++) {
        int px = sub * 32 + lane;
        float sx = X1 + (px + 0.5f) * DX;
        if (sx > -1.0f && sx < (float)HW) vmask |= (1u << sub);
        float cxc = fminf(fmaxf(sx, 0.0f), (float)(HW - 1));
        float fxl = floorf(cxc);
        xps[sub] = min(max((int)fxl - x_lo, 0), 31);
        fxs[sub] = cxc - fxl;
        float txc = (px + 0.5f) * ((float)AR / (float)HW) - 0.5f;
        txc = fminf(fmaxf(txc, 0.0f), (float)(AR - 1));
        float ftx = floorf(txc);
        cxs[sub] = (int)ftx;
        wcxs[sub] = txc - ftx;
    }

    const size_t obase = (size_t)(b * MAXDET + det) * OUTROW + 6;

    for (int py = wid; py < HW; py += 16) {
        float sy = Y1 + (py + 0.5f) * DY;
        bool  vy = (sy > -1.0f) && (sy < (float)HW);
        float cyc = fminf(fmaxf(sy, 0.0f), (float)(HW - 1));
        float fyl = floorf(cyc);
        int   y0p = min(max((int)fyl - y_lo, 0), 31);
        int   y1p = min(max(min((int)fyl + 1, HW - 1) - y_lo, 0), 31);
        float fy  = cyc - fyl;

#pragma unroll
        for (int c = 0; c < 5; c++) {
            float a0 = patch[(c * 32 + y0p) * 33 + lane];
            float a1 = patch[(c * 32 + y1p) * 33 + lane];
            float rv = fmaf(a1 - a0, fy, a0);
            float rn = __shfl_down_sync(0xFFFFFFFFu, rv, 1);
            rows2[c * 32 + lane] = make_float2(rv, rn);
        }

        float tyc = (py + 0.5f) * ((float)AR / (float)HW) - 0.5f;
        tyc = fminf(fmaxf(tyc, 0.0f), (float)(AR - 1));
        float fty = floorf(tyc);
        int cy0 = (int)fty, cy1 = min(cy0 + 1, AR - 1);
        float wy2 = tyc - fty;
        for (int i = lane; i < 75; i += 32) {
            int c = i / 15, k = i - c * 15;
            int ka = min(k, AR - 1), kb = min(k + 1, AR - 1);
            float a0 = sA[c * 196 + cy0 * AR + ka], a1 = sA[c * 196 + cy1 * AR + ka];
            float b0 = sA[c * 196 + cy0 * AR + kb], b1 = sA[c * 196 + cy1 * AR + kb];
            tw2[c * 15 + k] = make_float2(fmaf(a1 - a0, wy2, a0), fmaf(b1 - b0, wy2, b0));
        }
        __syncwarp();

#pragma unroll
        for (int sub = 0; sub < 5; sub++) {
            int   xp  = xps[sub];
            int   cxi = cxs[sub];
            float fx  = fxs[sub];
            float wcx = wcxs[sub];

            // channel 0 is the softmax pivot (e0 = 1)
            float2 tt0 = tw2[cxi];
            float  co0 = fmaf(tt0.y - tt0.x, wcx, tt0.x);
            float2 rv0 = rows2[xp];
            float  acc = fmaf(rv0.y - rv0.x, fx, rv0.x);
            float  esum = 1.f;
#pragma unroll
            for (int c = 1; c < 5; c++) {
                float2 tt = tw2[c * 15 + cxi];
                float e = __expf(fmaf(tt.y - tt.x, wcx, tt.x) - co0);
                esum += e;
                float2 rv = rows2[c * 32 + xp];
                acc = fmaf(fmaf(rv.y - rv.x, fx, rv.x), e, acc);
            }
            acc = (((vmask >> sub) & 1u) && vy) ? acc : 0.f;
            float z = __fdividef(acc, esum);
            out[obase + (size_t)py * HW + sub * 32 + lane] =
                fmaf(0.5f, tanh_approx(0.5f * z), 0.5f);
        }
        __syncwarp();
    }
}

// ---------------- launch ----------------------------------------------------
extern "C" void kernel_launch(void* const* d_in, const int* in_sizes, int n_in,
                              void* d_out, int out_size) {
    const float *test = nullptr, *attn = nullptr, *bases = nullptr, *sem = nullptr;
    for (int i = 0; i < n_in; i++) {
        long long s = in_sizes[i];
        if      (s == (long long)NBATCH * NA * ROWF)   test  = (const float*)d_in[i];
        else if (s == (long long)NBATCH * NA * ATTNF)  attn  = (const float*)d_in[i];
        else if (s == (long long)NBATCH * 4 * HW * HW) bases = (const float*)d_in[i];
        else if (s == (long long)NBATCH * 1 * HW * HW) sem   = (const float*)d_in[i];
    }
    float* out = (float*)d_out;

    cudaFuncSetAttribute(k_masks, cudaFuncAttributeMaxDynamicSharedMemorySize, MSK_SMEM_BYTES);

    k_pre<<<(NBATCH * SCB) / 256, 256>>>(test);
    k_sortnms<<<NBATCH, 1024>>>(test, out);
    k_masks<<<dim3(MAXDET, NBATCH), 512, MSK_SMEM_BYTES>>>(test, attn, bases, sem, out);
}

// round 12
// speedup vs baseline: 1.0244x; 1.0244x over previous
#include <cuda_runtime.h>
#include <cstdint>

#define NBATCH 4
#define NA 25200
#define NCLS 80
#define ROWF 85
#define ATTNF 980
#define AR 14
#define CONF 0.25f
#define IOUT 0.45f
#define MAXDET 100
#define TOPK 1024
#define HB 256
#define MAXC 2048
#define PRECAP 16384
#define PREV 0.9f
#define HW 160
#define OUTROW 25606
#define TILE_A 60
#define SCB (NA * NCLS)          // 2,016,000 scores per batch

// ---------------- scratch (device globals; zero-init at load) ---------------
__device__ int                g_preCnt[NBATCH];
__device__ unsigned long long g_preKey[NBATCH * PRECAP];
__device__ int                g_detAnchor[NBATCH * MAXDET];

// ---------------- pass 1: tiled streaming prefilter (v > 0.9) ---------------
__global__ void __launch_bounds__(256) k_pre(const float* __restrict__ test) {
    __shared__ float4 tile4[TILE_A * ROWF / 4];
    float* tile = (float*)tile4;
    const int b   = blockIdx.y;
    const int tid = blockIdx.x;
    const int t   = threadIdx.x;
    const float4* src = (const float4*)(test + ((size_t)b * NA + (size_t)tid * TILE_A) * ROWF);
#pragma unroll
    for (int i = t; i < TILE_A * ROWF / 4; i += 256) tile4[i] = src[i];
    __syncthreads();
    for (int i = t; i < TILE_A * NCLS; i += 256) {
        int a = i / NCLS, c = i - a * NCLS;
        float v = tile[a * ROWF + 5 + c] * tile[a * ROWF + 4];
        if (v > PREV) {
            int pos = atomicAdd(&g_preCnt[b], 1);
            if (pos < PRECAP) {
                unsigned flat = (unsigned)((tid * TILE_A + a) * NCLS + c);
                g_preKey[b * PRECAP + pos] =
                    ((unsigned long long)__float_as_uint(v) << 32) |
                    (unsigned long long)(0xFFFFFFFFu - flat);
            }
        }
    }
}

// ---------------- hybrid bitonic helpers ------------------------------------
__device__ __forceinline__ unsigned long long cex_shfl(unsigned long long v, int i, int j, int k) {
    unsigned long long pv = __shfl_xor_sync(0xFFFFFFFFu, v, j);
    bool lower = ((i & j) == 0);
    bool desc  = ((i & k) == 0);
    return (desc == lower) ? (v > pv ? v : pv) : (v < pv ? v : pv);
}
__device__ __forceinline__ void cex_reg(unsigned long long& v0, unsigned long long& v1, int i0, int k) {
    bool desc = ((i0 & k) == 0);
    unsigned long long a = v0, b = v1;
    if (desc ? (a < b) : (a > b)) { v0 = b; v1 = a; }
}

// ---------------- hist + filter + bitonic sort + greedy NMS -----------------
union SortU {
    unsigned long long s[MAXC];
    struct { int cls[TOPK]; int anc[TOPK]; } post;
};

__global__ void __launch_bounds__(1024, 1) k_sortnms(const float* __restrict__ test,
                                                     float* __restrict__ out) {
    __shared__ SortU u;
    __shared__ float sbx1[TOPK], sby1[TOPK], sbx2[TOPK], sby2[TOPK], sar[TOPK], sval[TOPK];
    __shared__ unsigned int hh[HB];
    __shared__ unsigned int vword[TOPK / 32];
    __shared__ int sel[MAXDET];
    __shared__ int s_thr, s_cnt;
    const int b = blockIdx.x;
    const int t = threadIdx.x;
    const int lane = t & 31, wid = t >> 5;
    const int base = wid * 64;
    const int i0 = base + lane, i1 = base + 32 + lane;

    if (t < HB) hh[t] = 0u;
    if (t == 0) s_cnt = 0;
    __syncthreads();

    const int rawCnt = g_preCnt[b];
    const int n = rawCnt > PRECAP ? PRECAP : rawCnt;
    const bool usePre = (rawCnt <= PRECAP) && (rawCnt >= TOPK);

    // phase 1: histogram
    if (usePre) {
        for (int i = t; i < n; i += 1024) {
            float v = __uint_as_float((unsigned)(g_preKey[b * PRECAP + i] >> 32));
            int bin = (int)(v * 256.0f); bin = bin > 255 ? 255 : bin;
            atomicAdd(&hh[bin], 1u);
        }
    } else {
        const float* tb = test + (size_t)b * NA * ROWF;
        for (int i = t; i < SCB; i += 1024) {
            int a = i / NCLS, c = i - a * NCLS;
            float v = tb[a * ROWF + 5 + c] * tb[a * ROWF + 4];
            if (v > CONF) {
                int bin = (int)(v * 256.0f); bin = bin > 255 ? 255 : bin;
                atomicAdd(&hh[bin], 1u);
            }
        }
    }
    __syncthreads();

    // phase 2: threshold bin (warp 0): highest bin whose suffix >= TOPK
    if (t < 32) {
        unsigned h[8];
#pragma unroll
        for (int k = 0; k < 8; k++) h[k] = hh[lane * 8 + k];
        unsigned tot = 0;
#pragma unroll
        for (int k = 0; k < 8; k++) tot += h[k];
        unsigned run = tot;
#pragma unroll
        for (int off = 1; off < 32; off <<= 1) {
            unsigned v = __shfl_down_sync(0xFFFFFFFFu, run, off);
            if (lane + off < 32) run += v;
        }
        unsigned above = run - tot;
        int cand = -1;
        unsigned cum = above;
        for (int k = 7; k >= 0; k--) {
            cum += h[k];
            if (cum >= TOPK) { cand = lane * 8 + k; break; }
        }
#pragma unroll
        for (int off = 16; off > 0; off >>= 1)
            cand = max(cand, __shfl_xor_sync(0xFFFFFFFFu, cand, off));
        if (lane == 0) s_thr = cand < 0 ? 0 : cand;
    }
    __syncthreads();
    const int thr = s_thr;

    // phase 3: gather candidates with bin >= thr
    if (usePre) {
        for (int i = t; i < n; i += 1024) {
            unsigned long long key = g_preKey[b * PRECAP + i];
            float v = __uint_as_float((unsigned)(key >> 32));
            int bin = (int)(v * 256.0f); bin = bin > 255 ? 255 : bin;
            if (bin >= thr) {
                int pos = atomicAdd(&s_cnt, 1);
                if (pos < MAXC) u.s[pos] = key;
            }
        }
    } else {
        const float* tb = test + (size_t)b * NA * ROWF;
        for (int i = t; i < SCB; i += 1024) {
            int a = i / NCLS, c = i - a * NCLS;
            float v = tb[a * ROWF + 5 + c] * tb[a * ROWF + 4];
            if (v > CONF) {
                int bin = (int)(v * 256.0f); bin = bin > 255 ? 255 : bin;
                if (bin >= thr) {
                    int pos = atomicAdd(&s_cnt, 1);
                    if (pos < MAXC)
                        u.s[pos] = ((unsigned long long)__float_as_uint(v) << 32) |
                                   (unsigned long long)(0xFFFFFFFFu - (unsigned)i);
                }
            }
        }
    }
    __syncthreads();
    int cnt = s_cnt; if (cnt > MAXC) cnt = MAXC;
    for (int i = t; i < MAXC; i += 1024)
        if (i >= cnt) u.s[i] = 0x00000000FFFFFFFFull;
    __syncthreads();

    // bitonic sort 2048 (hybrid: warp-local j<=32, smem j>=64)
    unsigned long long v0 = u.s[i0];
    unsigned long long v1 = u.s[i1];
#pragma unroll
    for (int k = 2; k <= 64; k <<= 1) {
#pragma unroll
        for (int j = k >> 1; j >= 1; j >>= 1) {
            if (j == 32) cex_reg(v0, v1, i0, k);
            else { v0 = cex_shfl(v0, i0, j, k); v1 = cex_shfl(v1, i1, j, k); }
        }
    }
    u.s[i0] = v0; u.s[i1] = v1;
    __syncthreads();
    for (int k = 128; k <= MAXC; k <<= 1) {
        for (int j = k >> 1; j >= 64; j >>= 1) {
#pragma unroll
            for (int i = t; i < MAXC; i += 1024) {
                int ixj = i ^ j;
                if (ixj > i) {
                    unsigned long long a = u.s[i], bb = u.s[ixj];
                    bool up = (i & k) == 0;
                    if (up ? (a < bb) : (a > bb)) { u.s[i] = bb; u.s[ixj] = a; }
                }
            }
            __syncthreads();
        }
        v0 = u.s[i0]; v1 = u.s[i1];
        cex_reg(v0, v1, i0, k);
#pragma unroll
        for (int j = 16; j >= 1; j >>= 1) {
            v0 = cex_shfl(v0, i0, j, k);
            v1 = cex_shfl(v1, i1, j, k);
        }
        u.s[i0] = v0; u.s[i1] = v1;
        __syncthreads();
    }

    unsigned long long key = u.s[t];
    __syncthreads();

    float v = __uint_as_float((unsigned)(key >> 32));
    unsigned flat = 0xFFFFFFFFu - (unsigned)(key & 0xFFFFFFFFull);
    bool valid = v > CONF;
    int anc = valid ? (int)(flat / NCLS) : 0;
    int cls = valid ? (int)(flat - (unsigned)anc * NCLS) : 0;

    const float* r = test + ((size_t)b * NA + anc) * ROWF;
    float cx = r[0], cy = r[1], w = r[2], h = r[3];
    float x1 = cx - 0.5f * w, y1 = cy - 0.5f * h;
    float x2 = cx + 0.5f * w, y2 = cy + 0.5f * h;
    sbx1[t] = x1; sby1[t] = y1; sbx2[t] = x2; sby2[t] = y2;
    sar[t] = fmaxf(x2 - x1, 0.f) * fmaxf(y2 - y1, 0.f);
    sval[t] = v; u.post.cls[t] = cls; u.post.anc[t] = anc;

    unsigned bal = __ballot_sync(0xFFFFFFFFu, valid);
    if (lane == 0) vword[wid] = bal;

    // zero scratch for next replay
    if (t == 0) g_preCnt[b] = 0;
    __syncthreads();

    for (int det = 0; det < MAXDET; det++) {
        unsigned m   = vword[lane];
        unsigned act = __ballot_sync(0xFFFFFFFFu, m != 0);
        int wsel = act ? (__ffs(act) - 1) : 0;
        unsigned mw = __shfl_sync(0xFFFFFFFFu, m, wsel);
        int j = act ? (wsel * 32 + __ffs(mw) - 1) : -1;
        if (t == 0) sel[det] = j;

        bool sup = false;
        if (j >= 0 && ((vword[wid] >> lane) & 1u)) {
            if (t == j) sup = true;
            else if (cls == u.post.cls[j]) {
                float lx = fmaxf(x1, sbx1[j]), ly = fmaxf(y1, sby1[j]);
                float rx = fminf(x2, sbx2[j]), ry = fminf(y2, sby2[j]);
                float iw = fmaxf(rx - lx, 0.f), ih = fmaxf(ry - ly, 0.f);
                float inter = iw * ih;
                float iou = inter / (sar[t] + sar[j] - inter + 1e-9f);
                sup = iou > IOUT;
            }
        }
        unsigned sm = __ballot_sync(0xFFFFFFFFu, sup);
        if (lane == 0) vword[wid] &= ~sm;
        __syncthreads();
    }

    // parallel epilogue: det headers
    if (t < MAXDET) {
        int j = sel[t];
        size_t ob = (size_t)(b * MAXDET + t) * OUTROW;
        if (j >= 0) {
            out[ob + 0] = sbx1[j]; out[ob + 1] = sby1[j];
            out[ob + 2] = sbx2[j]; out[ob + 3] = sby2[j];
            out[ob + 4] = sval[j]; out[ob + 5] = (float)u.post.cls[j];
            g_detAnchor[b * MAXDET + t] = u.post.anc[j];
        } else {
            out[ob+0]=0.f; out[ob+1]=0.f; out[ob+2]=0.f;
            out[ob+3]=0.f; out[ob+4]=0.f; out[ob+5]=0.f;
            g_detAnchor[b * MAXDET + t] = 0;
        }
    }
}

// ---------------- masks: 1 det/block, reg x-params, reduced MUFU ------------
// dynamic smem (floats): sA 0..980 | patch 980..6260 | per-warp 16*470
#define MSK_SMEM_FLOATS (6260 + 16 * 470)
#define MSK_SMEM_BYTES  (MSK_SMEM_FLOATS * 4)

__device__ __forceinline__ float tanh_approx(float x) {
    float r;
    asm("tanh.approx.f32 %0, %1;" : "=f"(r) : "f"(x));
    return r;
}

__global__ void __launch_bounds__(512, 3) k_masks(const float* __restrict__ test,
                        const float* __restrict__ attn,
                        const float* __restrict__ bases,
                        const float* __restrict__ sem,
                        float* __restrict__ out) {
    extern __shared__ float dyn[];
    float* sA    = dyn;
    float* patch = dyn + 980;
    const int b   = blockIdx.y;
    const int det = blockIdx.x;
    const int t   = threadIdx.x;
    const int lane = t & 31, wid = t >> 5;
    const int anc = g_detAnchor[b * MAXDET + det];

    float2* rows2 = (float2*)(dyn + 6260 + wid * 470);        // 160 float2
    float2* tw2   = (float2*)(dyn + 6260 + wid * 470 + 320);  // 75 float2

    const float* r = test + ((size_t)b * NA + anc) * ROWF;
    float cx = __ldg(r), cy = __ldg(r + 1), w = __ldg(r + 2), h = __ldg(r + 3);
    float bx1 = cx - 0.5f * w, by1 = cy - 0.5f * h;
    float bx2 = cx + 0.5f * w, by2 = cy + 0.5f * h;
    float X1 = bx1 * 0.25f - 0.5f, Y1 = by1 * 0.25f - 0.5f;
    float X2 = bx2 * 0.25f - 0.5f, Y2 = by2 * 0.25f - 0.5f;
    float DX = (X2 - X1) / (float)HW;
    float DY = (Y2 - Y1) / (float)HW;

    float sxa = X1 + 0.5f * DX;
    int x_lo  = (int)floorf(fminf(fmaxf(sxa, 0.f), 159.f));
    float sya = Y1 + 0.5f * DY;
    int y_lo  = (int)floorf(fminf(fmaxf(sya, 0.f), 159.f));

    {
        const float4* ap = (const float4*)(attn + ((size_t)b * NA + anc) * ATTNF);
        for (int i = t; i < ATTNF / 4; i += 512) ((float4*)sA)[i] = ap[i];
    }
#pragma unroll
    for (int c = 0; c < 5; c++) {
        const float* F = (c < 4) ? bases + (size_t)(b * 4 + c) * (HW * HW)
                                 : sem + (size_t)b * (HW * HW);
        for (int i = t; i < 32 * 32; i += 512) {
            int yy = i >> 5, xx = i & 31;
            int gy = min(y_lo + yy, HW - 1);
            int gx = min(x_lo + xx, HW - 1);
            patch[(c * 32 + yy) * 33 + xx] = __ldg(F + gy * HW + gx);
        }
    }
    __syncthreads();

    // per-thread x params (fixed across rows)
    float fxs[5], wcxs[5];
    int   xps[5], cxs[5];
    unsigned vmask = 0;
#pragma unroll
    for (int sub = 0; sub < 5; sub++) {
        int px = sub * 32 + lane;
        float sx = X1 + (px + 0.5f) * DX;
        if (sx > -1.0f && sx < (float)HW) vmask |= (1u << sub);
        float cxc = fminf(fmaxf(sx, 0.0f), (float)(HW - 1));
        float fxl = floorf(cxc);
        xps[sub] = min(max((int)fxl - x_lo, 0), 31);
        fxs[sub] = cxc - fxl;
        float txc = (px + 0.5f) * ((float)AR / (float)HW) - 0.5f;
        txc = fminf(fmaxf(txc, 0.0f), (float)(AR - 1));
        float ftx = floorf(txc);
        cxs[sub] = (int)ftx;
        wcxs[sub] = txc - ftx;
    }

    const size_t obase = (size_t)(b * MAXDET + det) * OUTROW + 6;

    for (int py = wid; py < HW; py += 16) {
        float sy = Y1 + (py + 0.5f) * DY;
        bool  vy = (sy > -1.0f) && (sy < (float)HW);
        float cyc = fminf(fmaxf(sy, 0.0f), (float)(HW - 1));
        float fyl = floorf(cyc);
        int   y0p = min(max((int)fyl - y_lo, 0), 31);
        int   y1p = min(max(min((int)fyl + 1, HW - 1) - y_lo, 0), 31);
        float fy  = cyc - fyl;

#pragma unroll
        for (int c = 0; c < 5; c++) {
            float a0 = patch[(c * 32 + y0p) * 33 + lane];
            float a1 = patch[(c * 32 + y1p) * 33 + lane];
            float rv = fmaf(a1 - a0, fy, a0);
            float rn = __shfl_down_sync(0xFFFFFFFFu, rv, 1);
            rows2[c * 32 + lane] = make_float2(rv, rn);
        }

        float tyc = (py + 0.5f) * ((float)AR / (float)HW) - 0.5f;
        tyc = fminf(fmaxf(tyc, 0.0f), (float)(AR - 1));
        float fty = floorf(tyc);
        int cy0 = (int)fty, cy1 = min(cy0 + 1, AR - 1);
        float wy2 = tyc - fty;
        for (int i = lane; i < 75; i += 32) {
            int c = i / 15, k = i - c * 15;
            int ka = min(k, AR - 1), kb = min(k + 1, AR - 1);
            float a0 = sA[c * 196 + cy0 * AR + ka], a1 = sA[c * 196 + cy1 * AR + ka];
            float b0 = sA[c * 196 + cy0 * AR + kb], b1 = sA[c * 196 + cy1 * AR + kb];
            tw2[c * 15 + k] = make_float2(fmaf(a1 - a0, wy2, a0), fmaf(b1 - b0, wy2, b0));
        }
        __syncwarp();

#pragma unroll
        for (int sub = 0; sub < 5; sub++) {
            int   xp  = xps[sub];
            int   cxi = cxs[sub];
            float fx  = fxs[sub];
            float wcx = wcxs[sub];

            // channel 0 is the softmax pivot (e0 = 1)
            float2 tt0 = tw2[cxi];
            float  co0 = fmaf(tt0.y - tt0.x, wcx, tt0.x);
            float2 rv0 = rows2[xp];
            float  acc = fmaf(rv0.y - rv0.x, fx, rv0.x);
            float  esum = 1.f;
#pragma unroll
            for (int c = 1; c < 5; c++) {
                float2 tt = tw2[c * 15 + cxi];
                float e = __expf(fmaf(tt.y - tt.x, wcx, tt.x) - co0);
                esum += e;
                float2 rv = rows2[c * 32 + xp];
                acc = fmaf(fmaf(rv.y - rv.x, fx, rv.x), e, acc);
            }
            acc = (((vmask >> sub) & 1u) && vy) ? acc : 0.f;
            float z = __fdividef(acc, esum);
            out[obase + (size_t)py * HW + sub * 32 + lane] =
                fmaf(0.5f, tanh_approx(0.5f * z), 0.5f);
        }
        __syncwarp();
    }
}

// ---------------- launch ----------------------------------------------------
extern "C" void kernel_launch(void* const* d_in, const int* in_sizes, int n_in,
                              void* d_out, int out_size) {
    const float *test = nullptr, *attn = nullptr, *bases = nullptr, *sem = nullptr;
    for (int i = 0; i < n_in; i++) {
        long long s = in_sizes[i];
        if      (s == (long long)NBATCH * NA * ROWF)   test  = (const float*)d_in[i];
        else if (s == (long long)NBATCH * NA * ATTNF)  attn  = (const float*)d_in[i];
        else if (s == (long long)NBATCH * 4 * HW * HW) bases = (const float*)d_in[i];
        else if (s == (long long)NBATCH * 1 * HW * HW) sem   = (const float*)d_in[i];
    }
    float* out = (float*)d_out;

    cudaFuncSetAttribute(k_masks, cudaFuncAttributeMaxDynamicSharedMemorySize, MSK_SMEM_BYTES);

    k_pre<<<dim3(NA / TILE_A, NBATCH), 256>>>(test);
    k_sortnms<<<NBATCH, 1024>>>(test, out);
    k_masks<<<dim3(MAXDET, NBATCH), 512, MSK_SMEM_BYTES>>>(test, attn, bases, sem, out);
}

// round 13
// speedup vs baseline: 1.0969x; 1.0708x over previous
#include <cuda_runtime.h>
#include <cstdint>

#define NBATCH 4
#define NA 25200
#define NCLS 80
#define ROWF 85
#define ATTNF 980
#define AR 14
#define CONF 0.25f
#define IOUT 0.45f
#define MAXDET 100
#define TOPK 1024
#define HB 256
#define MAXC 2048
#define PRECAP 16384
#define PREV 0.9f
#define HW 160
#define OUTROW 25606
#define TILE_A 60
#define WCAP 512
#define SCB (NA * NCLS)          // 2,016,000 scores per batch

// ---------------- scratch (device globals; zero-init at load) ---------------
__device__ int                g_preCnt[NBATCH];
__device__ int                g_ovf[NBATCH];
__device__ unsigned long long g_preKey[NBATCH * PRECAP];
__device__ int                g_detAnchor[NBATCH * MAXDET];

// ---------------- pass 1: tiled prefilter, block-aggregated append ----------
__global__ void __launch_bounds__(256) k_pre(const float* __restrict__ test) {
    __shared__ float4 tile4[TILE_A * ROWF / 4];
    __shared__ unsigned long long wlist[WCAP];
    __shared__ int wcnt, gbase;
    float* tile = (float*)tile4;
    const int b   = blockIdx.y;
    const int tid = blockIdx.x;
    const int t   = threadIdx.x;
    if (t == 0) wcnt = 0;
    const float4* src = (const float4*)(test + ((size_t)b * NA + (size_t)tid * TILE_A) * ROWF);
#pragma unroll
    for (int i = t; i < TILE_A * ROWF / 4; i += 256) tile4[i] = src[i];
    __syncthreads();
    for (int i = t; i < TILE_A * NCLS; i += 256) {
        int a = i / NCLS, c = i - a * NCLS;
        float v = tile[a * ROWF + 5 + c] * tile[a * ROWF + 4];
        if (v > PREV) {
            int p = atomicAdd(&wcnt, 1);
            if (p < WCAP) {
                unsigned flat = (unsigned)((tid * TILE_A + a) * NCLS + c);
                wlist[p] = ((unsigned long long)__float_as_uint(v) << 32) |
                           (unsigned long long)(0xFFFFFFFFu - flat);
            }
        }
    }
    __syncthreads();
    int cnt = wcnt;
    if (cnt > WCAP) {                 // dropped keys -> force fallback path
        if (t == 0) g_ovf[b] = 1;
        cnt = WCAP;
    }
    if (t == 0) gbase = (cnt > 0) ? atomicAdd(&g_preCnt[b], cnt) : 0;
    __syncthreads();
    const int base = gbase;
    for (int i = t; i < cnt; i += 256) {
        int pos = base + i;
        if (pos < PRECAP) g_preKey[b * PRECAP + pos] = wlist[i];
    }
}

// ---------------- hybrid bitonic helpers ------------------------------------
__device__ __forceinline__ unsigned long long cex_shfl(unsigned long long v, int i, int j, int k) {
    unsigned long long pv = __shfl_xor_sync(0xFFFFFFFFu, v, j);
    bool lower = ((i & j) == 0);
    bool desc  = ((i & k) == 0);
    return (desc == lower) ? (v > pv ? v : pv) : (v < pv ? v : pv);
}
__device__ __forceinline__ void cex_reg(unsigned long long& v0, unsigned long long& v1, int i0, int k) {
    bool desc = ((i0 & k) == 0);
    unsigned long long a = v0, b = v1;
    if (desc ? (a < b) : (a > b)) { v0 = b; v1 = a; }
}

// ---------------- hist + filter + bitonic sort + greedy NMS -----------------
union SortU {
    unsigned long long s[MAXC];
    struct { int cls[TOPK]; int anc[TOPK]; } post;
};

__global__ void __launch_bounds__(1024, 1) k_sortnms(const float* __restrict__ test,
                                                     float* __restrict__ out) {
    __shared__ SortU u;
    __shared__ float sbx1[TOPK], sby1[TOPK], sbx2[TOPK], sby2[TOPK], sar[TOPK], sval[TOPK];
    __shared__ unsigned int hh[HB];
    __shared__ unsigned int vword[TOPK / 32];
    __shared__ int sel[MAXDET];
    __shared__ int s_thr, s_cnt;
    const int b = blockIdx.x;
    const int t = threadIdx.x;
    const int lane = t & 31, wid = t >> 5;
    const int base = wid * 64;
    const int i0 = base + lane, i1 = base + 32 + lane;

    if (t < HB) hh[t] = 0u;
    if (t == 0) s_cnt = 0;
    __syncthreads();

    const int rawCnt = g_preCnt[b];
    const int n = rawCnt > PRECAP ? PRECAP : rawCnt;
    const bool usePre = (rawCnt <= PRECAP) && (rawCnt >= TOPK) && (g_ovf[b] == 0);

    // phase 1: histogram (warp-aggregated per distinct bin)
    if (usePre) {
        int n_pad = (n + 1023) & ~1023;
        for (int i = t; i < n_pad; i += 1024) {
            bool act = i < n;
            unsigned amask = __ballot_sync(0xFFFFFFFFu, act);
            if (act) {
                float v = __uint_as_float((unsigned)(g_preKey[b * PRECAP + i] >> 32));
                int bin = (int)(v * 256.0f); bin = bin > 255 ? 255 : bin;
                unsigned grp = __match_any_sync(amask, bin);
                if (lane == __ffs(grp) - 1) atomicAdd(&hh[bin], __popc(grp));
            }
        }
    } else {
        const float* tb = test + (size_t)b * NA * ROWF;
        for (int i = t; i < SCB; i += 1024) {
            int a = i / NCLS, c = i - a * NCLS;
            float v = tb[a * ROWF + 5 + c] * tb[a * ROWF + 4];
            if (v > CONF) {
                int bin = (int)(v * 256.0f); bin = bin > 255 ? 255 : bin;
                atomicAdd(&hh[bin], 1u);
            }
        }
    }
    __syncthreads();

    // phase 2: threshold bin (warp 0): highest bin whose suffix >= TOPK
    if (t < 32) {
        unsigned h[8];
#pragma unroll
        for (int k = 0; k < 8; k++) h[k] = hh[lane * 8 + k];
        unsigned tot = 0;
#pragma unroll
        for (int k = 0; k < 8; k++) tot += h[k];
        unsigned run = tot;
#pragma unroll
        for (int off = 1; off < 32; off <<= 1) {
            unsigned v = __shfl_down_sync(0xFFFFFFFFu, run, off);
            if (lane + off < 32) run += v;
        }
        unsigned above = run - tot;
        int cand = -1;
        unsigned cum = above;
        for (int k = 7; k >= 0; k--) {
            cum += h[k];
            if (cum >= TOPK) { cand = lane * 8 + k; break; }
        }
#pragma unroll
        for (int off = 16; off > 0; off >>= 1)
            cand = max(cand, __shfl_xor_sync(0xFFFFFFFFu, cand, off));
        if (lane == 0) s_thr = cand < 0 ? 0 : cand;
    }
    __syncthreads();
    const int thr = s_thr;

    // phase 3: gather candidates with bin >= thr (ballot-aggregated append)
    if (usePre) {
        int n_pad = (n + 1023) & ~1023;
        for (int i = t; i < n_pad; i += 1024) {
            bool act = i < n;
            unsigned long long key = act ? g_preKey[b * PRECAP + i] : 0ull;
            bool win = false;
            if (act) {
                float v = __uint_as_float((unsigned)(key >> 32));
                int bin = (int)(v * 256.0f); bin = bin > 255 ? 255 : bin;
                win = bin >= thr;
            }
            unsigned wmask = __ballot_sync(0xFFFFFFFFu, win);
            if (win) {
                int ldr = __ffs(wmask) - 1;
                int bpos;
                if (lane == ldr) bpos = atomicAdd(&s_cnt, __popc(wmask));
                bpos = __shfl_sync(wmask, bpos, ldr);
                int pos = bpos + __popc(wmask & ((1u << lane) - 1u));
                if (pos < MAXC) u.s[pos] = key;
            }
        }
    } else {
        const float* tb = test + (size_t)b * NA * ROWF;
        for (int i = t; i < SCB; i += 1024) {
            int a = i / NCLS, c = i - a * NCLS;
            float v = tb[a * ROWF + 5 + c] * tb[a * ROWF + 4];
            if (v > CONF) {
                int bin = (int)(v * 256.0f); bin = bin > 255 ? 255 : bin;
                if (bin >= thr) {
                    int pos = atomicAdd(&s_cnt, 1);
                    if (pos < MAXC)
                        u.s[pos] = ((unsigned long long)__float_as_uint(v) << 32) |
                                   (unsigned long long)(0xFFFFFFFFu - (unsigned)i);
                }
            }
        }
    }
    __syncthreads();
    int cnt = s_cnt; if (cnt > MAXC) cnt = MAXC;
    for (int i = t; i < MAXC; i += 1024)
        if (i >= cnt) u.s[i] = 0x00000000FFFFFFFFull;
    __syncthreads();

    // bitonic sort 2048 (hybrid: warp-local j<=32, smem j>=64)
    unsigned long long v0 = u.s[i0];
    unsigned long long v1 = u.s[i1];
#pragma unroll
    for (int k = 2; k <= 64; k <<= 1) {
#pragma unroll
        for (int j = k >> 1; j >= 1; j >>= 1) {
            if (j == 32) cex_reg(v0, v1, i0, k);
            else { v0 = cex_shfl(v0, i0, j, k); v1 = cex_shfl(v1, i1, j, k); }
        }
    }
    u.s[i0] = v0; u.s[i1] = v1;
    __syncthreads();
    for (int k = 128; k <= MAXC; k <<= 1) {
        for (int j = k >> 1; j >= 64; j >>= 1) {
#pragma unroll
            for (int i = t; i < MAXC; i += 1024) {
                int ixj = i ^ j;
                if (ixj > i) {
                    unsigned long long a = u.s[i], bb = u.s[ixj];
                    bool up = (i & k) == 0;
                    if (up ? (a < bb) : (a > bb)) { u.s[i] = bb; u.s[ixj] = a; }
                }
            }
            __syncthreads();
        }
        v0 = u.s[i0]; v1 = u.s[i1];
        cex_reg(v0, v1, i0, k);
#pragma unroll
        for (int j = 16; j >= 1; j >>= 1) {
            v0 = cex_shfl(v0, i0, j, k);
            v1 = cex_shfl(v1, i1, j, k);
        }
        u.s[i0] = v0; u.s[i1] = v1;
        __syncthreads();
    }

    unsigned long long key = u.s[t];
    __syncthreads();

    float v = __uint_as_float((unsigned)(key >> 32));
    unsigned flat = 0xFFFFFFFFu - (unsigned)(key & 0xFFFFFFFFull);
    bool valid = v > CONF;
    int anc = valid ? (int)(flat / NCLS) : 0;
    int cls = valid ? (int)(flat - (unsigned)anc * NCLS) : 0;

    const float* r = test + ((size_t)b * NA + anc) * ROWF;
    float cx = r[0], cy = r[1], w = r[2], h = r[3];
    float x1 = cx - 0.5f * w, y1 = cy - 0.5f * h;
    float x2 = cx + 0.5f * w, y2 = cy + 0.5f * h;
    sbx1[t] = x1; sby1[t] = y1; sbx2[t] = x2; sby2[t] = y2;
    sar[t] = fmaxf(x2 - x1, 0.f) * fmaxf(y2 - y1, 0.f);
    sval[t] = v; u.post.cls[t] = cls; u.post.anc[t] = anc;

    unsigned bal = __ballot_sync(0xFFFFFFFFu, valid);
    if (lane == 0) vword[wid] = bal;

    // zero scratch for next replay
    if (t == 0) { g_preCnt[b] = 0; g_ovf[b] = 0; }
    __syncthreads();

    for (int det = 0; det < MAXDET; det++) {
        unsigned m   = vword[lane];
        unsigned act = __ballot_sync(0xFFFFFFFFu, m != 0);
        int wsel = act ? (__ffs(act) - 1) : 0;
        unsigned mw = __shfl_sync(0xFFFFFFFFu, m, wsel);
        int j = act ? (wsel * 32 + __ffs(mw) - 1) : -1;
        if (t == 0) sel[det] = j;

        bool sup = false;
        if (j >= 0 && ((vword[wid] >> lane) & 1u)) {
            if (t == j) sup = true;
            else if (cls == u.post.cls[j]) {
                float lx = fmaxf(x1, sbx1[j]), ly = fmaxf(y1, sby1[j]);
                float rx = fminf(x2, sbx2[j]), ry = fminf(y2, sby2[j]);
                float iw = fmaxf(rx - lx, 0.f), ih = fmaxf(ry - ly, 0.f);
                float inter = iw * ih;
                float iou = inter / (sar[t] + sar[j] - inter + 1e-9f);
                sup = iou > IOUT;
            }
        }
        unsigned sm = __ballot_sync(0xFFFFFFFFu, sup);
        if (lane == 0) vword[wid] &= ~sm;
        __syncthreads();
    }

    // parallel epilogue: det headers
    if (t < MAXDET) {
        int j = sel[t];
        size_t ob = (size_t)(b * MAXDET + t) * OUTROW;
        if (j >= 0) {
            out[ob + 0] = sbx1[j]; out[ob + 1] = sby1[j];
            out[ob + 2] = sbx2[j]; out[ob + 3] = sby2[j];
            out[ob + 4] = sval[j]; out[ob + 5] = (float)u.post.cls[j];
            g_detAnchor[b * MAXDET + t] = u.post.anc[j];
        } else {
            out[ob+0]=0.f; out[ob+1]=0.f; out[ob+2]=0.f;
            out[ob+3]=0.f; out[ob+4]=0.f; out[ob+5]=0.f;
            g_detAnchor[b * MAXDET + t] = 0;
        }
    }
}

// ---------------- masks: 1 det/block, reg x-params, reduced MUFU ------------
// dynamic smem (floats): sA 0..980 | patch 980..6260 | per-warp 16*470
#define MSK_SMEM_FLOATS (6260 + 16 * 470)
#define MSK_SMEM_BYTES  (MSK_SMEM_FLOATS * 4)

__device__ __forceinline__ float tanh_approx(float x) {
    float r;
    asm("tanh.approx.f32 %0, %1;" : "=f"(r) : "f"(x));
    return r;
}

__global__ void __launch_bounds__(512, 3) k_masks(const float* __restrict__ test,
                        const float* __restrict__ attn,
                        const float* __restrict__ bases,
                        const float* __restrict__ sem,
                        float* __restrict__ out) {
    extern __shared__ float dyn[];
    float* sA    = dyn;
    float* patch = dyn + 980;
    const int b   = blockIdx.y;
    const int det = blockIdx.x;
    const int t   = threadIdx.x;
    const int lane = t & 31, wid = t >> 5;
    const int anc = g_detAnchor[b * MAXDET + det];

    float2* rows2 = (float2*)(dyn + 6260 + wid * 470);        // 160 float2
    float2* tw2   = (float2*)(dyn + 6260 + wid * 470 + 320);  // 75 float2

    const float* r = test + ((size_t)b * NA + anc) * ROWF;
    float cx = __ldg(r), cy = __ldg(r + 1), w = __ldg(r + 2), h = __ldg(r + 3);
    float bx1 = cx - 0.5f * w, by1 = cy - 0.5f * h;
    float bx2 = cx + 0.5f * w, by2 = cy + 0.5f * h;
    float X1 = bx1 * 0.25f - 0.5f, Y1 = by1 * 0.25f - 0.5f;
    float X2 = bx2 * 0.25f - 0.5f, Y2 = by2 * 0.25f - 0.5f;
    float DX = (X2 - X1) / (float)HW;
    float DY = (Y2 - Y1) / (float)HW;

    float sxa = X1 + 0.5f * DX;
    int x_lo  = (int)floorf(fminf(fmaxf(sxa, 0.f), 159.f));
    float sya = Y1 + 0.5f * DY;
    int y_lo  = (int)floorf(fminf(fmaxf(sya, 0.f), 159.f));

    {
        const float4* ap = (const float4*)(attn + ((size_t)b * NA + anc) * ATTNF);
        for (int i = t; i < ATTNF / 4; i += 512) ((float4*)sA)[i] = ap[i];
    }
#pragma unroll
    for (int c = 0; c < 5; c++) {
        const float* F = (c < 4) ? bases + (size_t)(b * 4 + c) * (HW * HW)
                                 : sem + (size_t)b * (HW * HW);
        for (int i = t; i < 32 * 32; i += 512) {
            int yy = i >> 5, xx = i & 31;
            int gy = min(y_lo + yy, HW - 1);
            int gx = min(x_lo + xx, HW - 1);
            patch[(c * 32 + yy) * 33 + xx] = __ldg(F + gy * HW + gx);
        }
    }
    __syncthreads();

    // per-thread x params (fixed across rows)
    float fxs[5], wcxs[5];
    int   xps[5], cxs[5];
    unsigned vmask = 0;
#pragma unroll
    for (int sub = 0; sub < 5; sub++) {
        int px = sub * 32 + lane;
        float sx = X1 + (px + 0.5f) * DX;
        if (sx > -1.0f && sx < (float)HW) vmask |= (1u << sub);
        float cxc = fminf(fmaxf(sx, 0.0f), (float)(HW - 1));
        float fxl = floorf(cxc);
        xps[sub] = min(max((int)fxl - x_lo, 0), 31);
        fxs[sub] = cxc - fxl;
        float txc = (px + 0.5f) * ((float)AR / (float)HW) - 0.5f;
        txc = fminf(fmaxf(txc, 0.0f), (float)(AR - 1));
        float ftx = floorf(txc);
        cxs[sub] = (int)ftx;
        wcxs[sub] = txc - ftx;
    }

    const size_t obase = (size_t)(b * MAXDET + det) * OUTROW + 6;

    for (int py = wid; py < HW; py += 16) {
        float sy = Y1 + (py + 0.5f) * DY;
        bool  vy = (sy > -1.0f) && (sy < (float)HW);
        float cyc = fminf(fmaxf(sy, 0.0f), (float)(HW - 1));
        float fyl = floorf(cyc);
        int   y0p = min(max((int)fyl - y_lo, 0), 31);
        int   y1p = min(max(min((int)fyl + 1, HW - 1) - y_lo, 0), 31);
        float fy  = cyc - fyl;

#pragma unroll
        for (int c = 0; c < 5; c++) {
            float a0 = patch[(c * 32 + y0p) * 33 + lane];
            float a1 = patch[(c * 32 + y1p) * 33 + lane];
            float rv = fmaf(a1 - a0, fy, a0);
            float rn = __shfl_down_sync(0xFFFFFFFFu, rv, 1);
            rows2[c * 32 + lane] = make_float2(rv, rn);
        }

        float tyc = (py + 0.5f) * ((float)AR / (float)HW) - 0.5f;
        tyc = fminf(fmaxf(tyc, 0.0f), (float)(AR - 1));
        float fty = floorf(tyc);
        int cy0 = (int)fty, cy1 = min(cy0 + 1, AR - 1);
        float wy2 = tyc - fty;
        for (int i = lane; i < 75; i += 32) {
            int c = i / 15, k = i - c * 15;
            int ka = min(k, AR - 1), kb = min(k + 1, AR - 1);
            float a0 = sA[c * 196 + cy0 * AR + ka], a1 = sA[c * 196 + cy1 * AR + ka];
            float b0 = sA[c * 196 + cy0 * AR + kb], b1 = sA[c * 196 + cy1 * AR + kb];
            tw2[c * 15 + k] = make_float2(fmaf(a1 - a0, wy2, a0), fmaf(b1 - b0, wy2, b0));
        }
        __syncwarp();

#pragma unroll
        for (int sub = 0; sub < 5; sub++) {
            int   xp  = xps[sub];
            int   cxi = cxs[sub];
            float fx  = fxs[sub];
            float wcx = wcxs[sub];

            // channel 0 is the softmax pivot (e0 = 1)
            float2 tt0 = tw2[cxi];
            float  co0 = fmaf(tt0.y - tt0.x, wcx, tt0.x);
            float2 rv0 = rows2[xp];
            float  acc = fmaf(rv0.y - rv0.x, fx, rv0.x);
            float  esum = 1.f;
#pragma unroll
            for (int c = 1; c < 5; c++) {
                float2 tt = tw2[c * 15 + cxi];
                float e = __expf(fmaf(tt.y - tt.x, wcx, tt.x) - co0);
                esum += e;
                float2 rv = rows2[c * 32 + xp];
                acc = fmaf(fmaf(rv.y - rv.x, fx, rv.x), e, acc);
            }
            acc = (((vmask >> sub) & 1u) && vy) ? acc : 0.f;
            float z = __fdividef(acc, esum);
            out[obase + (size_t)py * HW + sub * 32 + lane] =
                fmaf(0.5f, tanh_approx(0.5f * z), 0.5f);
        }
        __syncwarp();
    }
}

// ---------------- launch ----------------------------------------------------
extern "C" void kernel_launch(void* const* d_in, const int* in_sizes, int n_in,
                              void* d_out, int out_size) {
    const float *test = nullptr, *attn = nullptr, *bases = nullptr, *sem = nullptr;
    for (int i = 0; i < n_in; i++) {
        long long s = in_sizes[i];
        if      (s == (long long)NBATCH * NA * ROWF)   test  = (const float*)d_in[i];
        else if (s == (long long)NBATCH * NA * ATTNF)  attn  = (const float*)d_in[i];
        else if (s == (long long)NBATCH * 4 * HW * HW) bases = (const float*)d_in[i];
        else if (s == (long long)NBATCH * 1 * HW * HW) sem   = (const float*)d_in[i];
    }
    float* out = (float*)d_out;

    cudaFuncSetAttribute(k_masks, cudaFuncAttributeMaxDynamicSharedMemorySize, MSK_SMEM_BYTES);

    k_pre<<<dim3(NA / TILE_A, NBATCH), 256>>>(test);
    k_sortnms<<<NBATCH, 1024>>>(test, out);
    k_masks<<<dim3(MAXDET, NBATCH), 512, MSK_SMEM_BYTES>>>(test, attn, bases, sem, out);
}